// round 11
// baseline (speedup 1.0000x reference)
#include <cuda_runtime.h>
#include <cuda_bf16.h>
#include <math.h>
#include <stdint.h>

#define BTCH   2
#define SLEN   2048
#define HDIM   2304
#define NHQ    8
#define NKVH   4
#define HD     256
#define WIN    512
#define MTOK   4096      // B*S
#define QCOLS  2048      // NH*HD
#define KCOLS  1024      // NKV*HD

// ------------------------- scratch (device globals; no allocs allowed) ------
__device__ float g_q[MTOK * QCOLS];
__device__ float g_k[MTOK * KCOLS];
__device__ float g_v[MTOK * KCOLS];

// pre-split bf16 operands (GEMM)
__device__ __align__(16) __nv_bfloat16 g_hidH[MTOK * HDIM], g_hidL[MTOK * HDIM];
__device__ __align__(16) __nv_bfloat16 g_wqH[QCOLS * HDIM], g_wqL[QCOLS * HDIM];
__device__ __align__(16) __nv_bfloat16 g_wkH[KCOLS * HDIM], g_wkL[KCOLS * HDIM];
__device__ __align__(16) __nv_bfloat16 g_wvH[KCOLS * HDIM], g_wvL[KCOLS * HDIM];
__device__ __align__(16) __nv_bfloat16 g_woH[HDIM * QCOLS], g_woL[HDIM * QCOLS];
__device__ __align__(16) __nv_bfloat16 g_aoH[MTOK * QCOLS], g_aoL[MTOK * QCOLS];
// pre-split bf16 Q/K/V (attention)
__device__ __align__(16) __nv_bfloat16 g_qbH[MTOK * QCOLS], g_qbL[MTOK * QCOLS];
__device__ __align__(16) __nv_bfloat16 g_kbH[MTOK * KCOLS], g_kbL[MTOK * KCOLS];
__device__ __align__(16) __nv_bfloat16 g_vbH[MTOK * KCOLS], g_vbL[MTOK * KCOLS];

// ------------------------- helpers -----------------------------------------
__device__ __forceinline__ uint32_t sptr(const void* p) {
    return (uint32_t)__cvta_generic_to_shared(p);
}
__device__ __forceinline__ void ldsm_x4(uint32_t* r, uint32_t a) {
    asm volatile("ldmatrix.sync.aligned.m8n8.x4.shared.b16 {%0,%1,%2,%3}, [%4];"
        : "=r"(r[0]), "=r"(r[1]), "=r"(r[2]), "=r"(r[3]) : "r"(a));
}
__device__ __forceinline__ void ldsm_x4_t(uint32_t* r, uint32_t a) {
    asm volatile("ldmatrix.sync.aligned.m8n8.x4.trans.shared.b16 {%0,%1,%2,%3}, [%4];"
        : "=r"(r[0]), "=r"(r[1]), "=r"(r[2]), "=r"(r[3]) : "r"(a));
}
__device__ __forceinline__ void ldsm_x2(uint32_t* r, uint32_t a) {
    asm volatile("ldmatrix.sync.aligned.m8n8.x2.shared.b16 {%0,%1}, [%2];"
        : "=r"(r[0]), "=r"(r[1]) : "r"(a));
}
__device__ __forceinline__ void mma_bf16(float* c, const uint32_t* a, const uint32_t* b) {
    asm volatile("mma.sync.aligned.m16n8k16.row.col.f32.bf16.bf16.f32 "
        "{%0,%1,%2,%3}, {%4,%5,%6,%7}, {%8,%9}, {%0,%1,%2,%3};"
        : "+f"(c[0]), "+f"(c[1]), "+f"(c[2]), "+f"(c[3])
        : "r"(a[0]), "r"(a[1]), "r"(a[2]), "r"(a[3]), "r"(b[0]), "r"(b[1]));
}
__device__ __forceinline__ void cp_async16(uint32_t dst, const void* src) {
    asm volatile("cp.async.cg.shared.global [%0], [%1], 16;"
        :: "r"(dst), "l"(src) : "memory");
}
__device__ __forceinline__ void cp_commit() {
    asm volatile("cp.async.commit_group;" ::: "memory");
}
__device__ __forceinline__ void split_bf16(float v, __nv_bfloat16& h, __nv_bfloat16& l) {
    h = __float2bfloat16(v);
    l = __float2bfloat16(v - __bfloat162float(h));
}
// pack (x,y) -> bf16x2 hi-part + bf16x2 residual-part
__device__ __forceinline__ void pack_split(float x, float y, uint32_t& hp, uint32_t& lp) {
    uint32_t hh;
    asm("cvt.rn.bf16x2.f32 %0, %1, %2;" : "=r"(hh) : "f"(y), "f"(x));
    float xr = x - __uint_as_float(hh << 16);
    float yr = y - __uint_as_float(hh & 0xffff0000u);
    hp = hh;
    asm("cvt.rn.bf16x2.f32 %0, %1, %2;" : "=r"(lp) : "f"(yr), "f"(xr));
}

// ------------------------- GEMM (unchanged from R6 win) ---------------------
#define KC       32
#define ROWBF    40
#define TILE_B   (128 * ROWBF * 2)
#define STAGE_B  (4 * TILE_B)
#define GSMEM    (2 * STAGE_B)

__device__ __forceinline__ void gemm_load_chunk(
    char* stg, const __nv_bfloat16* Ah, const __nv_bfloat16* Al,
    const __nv_bfloat16* Bh, const __nv_bfloat16* Bl,
    int bm, int bn, int K, int k0, int tid)
{
    const __nv_bfloat16* bases[4] = {Ah, Al, Bh, Bl};
    #pragma unroll
    for (int j = 0; j < 8; j++) {
        const int tile = j >> 1;
        const int e = ((j & 1) << 8) + tid;
        const int row = e >> 2;
        const int c = e & 3;
        const int gr = (tile < 2 ? bm : bn) + row;
        const __nv_bfloat16* src = bases[tile] + (size_t)gr * K + k0 + (c << 3);
        uint32_t dst = sptr(stg + tile * TILE_B + row * (ROWBF * 2) + (c << 4));
        cp_async16(dst, src);
    }
    cp_commit();
}

__global__ void __launch_bounds__(256, 2) gemm_mma_kernel(
    const __nv_bfloat16* __restrict__ Ah, const __nv_bfloat16* __restrict__ Al,
    const __nv_bfloat16* __restrict__ Bh, const __nv_bfloat16* __restrict__ Bl,
    float* __restrict__ C, int M, int N, int K)
{
    extern __shared__ __align__(16) char smem[];
    const int tid  = threadIdx.x;
    const int lane = tid & 31;
    const int warp = tid >> 5;
    const int wm = warp >> 2;
    const int wn = warp & 3;
    const int bm = blockIdx.y * 128;
    const int bn = blockIdx.x * 128;

    float c[4][4][4];
    #pragma unroll
    for (int mt = 0; mt < 4; mt++)
        #pragma unroll
        for (int nt = 0; nt < 4; nt++)
            #pragma unroll
            for (int i = 0; i < 4; i++) c[mt][nt][i] = 0.f;

    const int NC = K / KC;
    gemm_load_chunk(smem, Ah, Al, Bh, Bl, bm, bn, K, 0, tid);

    for (int i = 0; i < NC; i++) {
        if (i + 1 < NC) {
            gemm_load_chunk(smem + ((i + 1) & 1) * STAGE_B,
                            Ah, Al, Bh, Bl, bm, bn, K, (i + 1) * KC, tid);
            asm volatile("cp.async.wait_group 1;" ::: "memory");
        } else {
            asm volatile("cp.async.wait_group 0;" ::: "memory");
        }
        __syncthreads();

        char* stg = smem + (i & 1) * STAGE_B;
        __nv_bfloat16 (*sAh)[ROWBF] = (__nv_bfloat16(*)[ROWBF])(stg);
        __nv_bfloat16 (*sAl)[ROWBF] = (__nv_bfloat16(*)[ROWBF])(stg + TILE_B);
        __nv_bfloat16 (*sBh)[ROWBF] = (__nv_bfloat16(*)[ROWBF])(stg + 2 * TILE_B);
        __nv_bfloat16 (*sBl)[ROWBF] = (__nv_bfloat16(*)[ROWBF])(stg + 3 * TILE_B);

        #pragma unroll
        for (int s = 0; s < 2; s++) {
            uint32_t bh[4][2], bl[4][2];
            const int b_r = lane & 7;
            const int b_c = s * 16 + (((lane >> 3) & 1) << 3);
            #pragma unroll
            for (int nt = 0; nt < 4; nt++) {
                ldsm_x2(bh[nt], sptr(&sBh[wn * 32 + nt * 8 + b_r][b_c]));
                ldsm_x2(bl[nt], sptr(&sBl[wn * 32 + nt * 8 + b_r][b_c]));
            }
            const int a_r = (lane & 7) | (((lane >> 3) & 1) << 3);
            const int a_c = s * 16 + (((lane >> 4) & 1) << 3);
            #pragma unroll
            for (int mt = 0; mt < 4; mt++) {
                uint32_t ah[4], al[4];
                ldsm_x4(ah, sptr(&sAh[wm * 64 + mt * 16 + a_r][a_c]));
                ldsm_x4(al, sptr(&sAl[wm * 64 + mt * 16 + a_r][a_c]));
                #pragma unroll
                for (int nt = 0; nt < 4; nt++) {
                    mma_bf16(c[mt][nt], ah, bh[nt]);
                    mma_bf16(c[mt][nt], ah, bl[nt]);
                    mma_bf16(c[mt][nt], al, bh[nt]);
                }
            }
        }
        __syncthreads();
    }

    #pragma unroll
    for (int mt = 0; mt < 4; mt++) {
        int row = bm + wm * 64 + mt * 16 + (lane >> 2);
        #pragma unroll
        for (int nt = 0; nt < 4; nt++) {
            int col = bn + wn * 32 + nt * 8 + ((lane & 3) << 1);
            *(float2*)(C + (size_t)row * N + col)       = make_float2(c[mt][nt][0], c[mt][nt][1]);
            *(float2*)(C + (size_t)(row + 8) * N + col) = make_float2(c[mt][nt][2], c[mt][nt][3]);
        }
    }
}

// ---------------------------------------------------------------------------
// fp32 -> hi/lo bf16 split
// ---------------------------------------------------------------------------
__global__ void split_kernel(const float* __restrict__ in,
                             __nv_bfloat16* __restrict__ oh,
                             __nv_bfloat16* __restrict__ ol, int n)
{
    int i = (blockIdx.x * blockDim.x + threadIdx.x) << 2;
    if (i >= n) return;
    float4 v = *(const float4*)(in + i);
    float vv[4] = {v.x, v.y, v.z, v.w};
    __nv_bfloat16 h[4], l[4];
    #pragma unroll
    for (int j = 0; j < 4; j++) split_bf16(vv[j], h[j], l[j]);
    *(uint2*)(oh + i) = *(uint2*)h;
    *(uint2*)(ol + i) = *(uint2*)l;
}

// ---------------------------------------------------------------------------
// weight transpose + split: [K][N] fp32 -> [N][K] hi/lo bf16
// ---------------------------------------------------------------------------
__global__ void transpose_split_kernel(const float* __restrict__ W,
                                       __nv_bfloat16* __restrict__ oh,
                                       __nv_bfloat16* __restrict__ ol,
                                       int K, int N)
{
    __shared__ float t[32][33];
    const int k0 = blockIdx.y << 5, n0 = blockIdx.x << 5;
    const int c = threadIdx.x & 31, r = threadIdx.x >> 5;
    #pragma unroll
    for (int it = 0; it < 4; it++) {
        int row = r + (it << 3);
        t[row][c] = W[(size_t)(k0 + row) * N + n0 + c];
    }
    __syncthreads();
    #pragma unroll
    for (int it = 0; it < 4; it++) {
        int n = r + (it << 3);
        float v = t[c][n];
        __nv_bfloat16 h, l;
        split_bf16(v, h, l);
        oh[(size_t)(n0 + n) * K + k0 + c] = h;
        ol[(size_t)(n0 + n) * K + k0 + c] = l;
    }
}

// ---------------------------------------------------------------------------
// RoPE on g_q/g_k fp32, writing split bf16 hi/lo directly.
// ---------------------------------------------------------------------------
__global__ void rope_split_kernel(const int* __restrict__ pos_ids,
    __nv_bfloat16* __restrict__ qbh, __nv_bfloat16* __restrict__ qbl,
    __nv_bfloat16* __restrict__ kbh, __nv_bfloat16* __restrict__ kbl)
{
    int idx = blockIdx.x * blockDim.x + threadIdx.x;
    if (idx >= MTOK * 12 * 128) return;
    int d  = idx & 127;
    int r  = idx >> 7;
    int hh = r % 12;
    int t  = r / 12;
    float pos = (float)pos_ids[t];
    float inv = __expf((float)d * -0.07195578415606394f);
    float ang = pos * inv;
    float sn, cs;
    sincosf(ang, &sn, &cs);
    const float* base;
    size_t ob;
    __nv_bfloat16 *oh, *ol;
    if (hh < 8) {
        base = g_q + (size_t)t * QCOLS + hh * HD;
        ob = (size_t)t * QCOLS + hh * HD + d;
        oh = qbh; ol = qbl;
    } else {
        base = g_k + (size_t)t * KCOLS + (hh - 8) * HD;
        ob = (size_t)t * KCOLS + (hh - 8) * HD + d;
        oh = kbh; ol = kbl;
    }
    float x1 = base[d];
    float x2 = base[d + 128];
    float y1 = x1 * cs - x2 * sn;
    float y2 = x2 * cs + x1 * sn;
    __nv_bfloat16 h1, l1, h2, l2;
    split_bf16(y1, h1, l1);
    split_bf16(y2, h2, l2);
    oh[ob] = h1; ol[ob] = l1;
    oh[ob + 128] = h2; ol[ob + 128] = l2;
}

// ---------------------------------------------------------------------------
// Tensor-core sliding-window flash attention, split-bf16.
// CTA: 64 queries, 8 warps. wq=warp&3 -> 16-q subtile; wd=warp>>2 -> d-half.
// Each warp computes full S (3-product split), fragment softmax, PV for its
// 128-d half (P split in regs, V split in smem). Output -> aoH/aoL bf16 split.
// ---------------------------------------------------------------------------
#define RSB        528                 // smem row stride bytes (264 bf16)
#define ATILE      (64 * RSB)          // 33792 per tensor-half
#define OQ_H       0
#define OQ_L       (1 * ATILE)
#define OK_H       (2 * ATILE)
#define OK_L       (3 * ATILE)
#define OV_H       (4 * ATILE)
#define OV_L       (5 * ATILE)
#define ATTN_SMEM  (6 * ATILE)         // 202752

__device__ __forceinline__ void attn_load_half(
    uint32_t dst, const __nv_bfloat16* src, int tid, int gstride)
{
    #pragma unroll
    for (int j = 0; j < 8; j++) {
        int e = tid + (j << 8);
        int row = e >> 5, c = e & 31;
        cp_async16(dst + row * RSB + (c << 4), src + (size_t)row * gstride + (c << 3));
    }
}

__global__ void __launch_bounds__(256, 1) attn_mma_kernel(
    const __nv_bfloat16* __restrict__ qbh, const __nv_bfloat16* __restrict__ qbl,
    const __nv_bfloat16* __restrict__ kbh, const __nv_bfloat16* __restrict__ kbl,
    const __nv_bfloat16* __restrict__ vbh, const __nv_bfloat16* __restrict__ vbl,
    __nv_bfloat16* __restrict__ aoH, __nv_bfloat16* __restrict__ aoL)
{
    extern __shared__ __align__(16) char smem[];
    const uint32_t sb = sptr(smem);
    const int qt = blockIdx.x, h = blockIdx.y, b = blockIdx.z;
    const int kvh = h >> 1;
    const int q0 = qt * 64;
    const int tid = threadIdx.x, lane = tid & 31, warp = tid >> 5;
    const int wq = warp & 3, wd = warp >> 2;

    const __nv_bfloat16* Qh = qbh + (size_t)(b * SLEN + q0) * QCOLS + h * HD;
    const __nv_bfloat16* Ql = qbl + (size_t)(b * SLEN + q0) * QCOLS + h * HD;
    const size_t kvbase = (size_t)(b * SLEN) * KCOLS + kvh * HD;

    // issue Q loads (group 0)
    attn_load_half(sb + OQ_H, Qh, tid, QCOLS);
    attn_load_half(sb + OQ_L, Ql, tid, QCOLS);
    cp_commit();

    const int kb_start = (qt >= 8) ? (qt - 8) : 0;
    // issue first K, V
    attn_load_half(sb + OK_H, kbh + kvbase + (size_t)kb_start * 64 * KCOLS, tid, KCOLS);
    attn_load_half(sb + OK_L, kbl + kvbase + (size_t)kb_start * 64 * KCOLS, tid, KCOLS);
    cp_commit();
    attn_load_half(sb + OV_H, vbh + kvbase + (size_t)kb_start * 64 * KCOLS, tid, KCOLS);
    attn_load_half(sb + OV_L, vbl + kvbase + (size_t)kb_start * 64 * KCOLS, tid, KCOLS);
    cp_commit();

    float o[16][4];
    #pragma unroll
    for (int i = 0; i < 16; i++)
        #pragma unroll
        for (int j = 0; j < 4; j++) o[i][j] = 0.f;
    float mrow[2] = {-1e30f, -1e30f};
    float lrow[2] = {0.f, 0.f};

    const int r0 = lane >> 2;
    // A-fragment addresses (Q): identical pattern to proven GEMM A loads
    const int a_r = (lane & 7) | (((lane >> 3) & 1) << 3);
    const int a_c = ((lane >> 4) & 1) << 3;
    const uint32_t qha = sb + OQ_H + (wq * 16 + a_r) * RSB + a_c * 2;
    const uint32_t qla = sb + OQ_L + (wq * 16 + a_r) * RSB + a_c * 2;
    // B-fragment addresses (K): x4 covering 2 n-tiles
    const int k_r = ((lane >> 4) << 3) + (lane & 7);
    const int k_c = ((lane >> 3) & 1) << 3;
    // V trans-fragment addresses
    const int v_r = (((lane >> 3) & 1) << 3) + (lane & 7);
    const int v_c = ((lane >> 4) & 1) << 3;

    for (int kb = kb_start; kb <= qt; kb++) {
        asm volatile("cp.async.wait_group 1;" ::: "memory");   // Q(+)K ready
        __syncthreads();

        // ---- S = Q K^T, full d, 3-product split ----
        float s[8][4];
        #pragma unroll
        for (int i = 0; i < 8; i++)
            #pragma unroll
            for (int j = 0; j < 4; j++) s[i][j] = 0.f;

        #pragma unroll 2
        for (int ks = 0; ks < 16; ks++) {
            uint32_t aH[4], aL[4];
            ldsm_x4(aH, qha + ks * 32);
            ldsm_x4(aL, qla + ks * 32);
            #pragma unroll
            for (int np = 0; np < 4; np++) {
                uint32_t bH[4], bL[4];
                uint32_t ka = sb + OK_H + (np * 16 + k_r) * RSB + (ks * 16 + k_c) * 2;
                ldsm_x4(bH, ka);
                ldsm_x4(bL, ka + ATILE);
                mma_bf16(s[2 * np],     aH, &bH[0]);
                mma_bf16(s[2 * np],     aH, &bL[0]);
                mma_bf16(s[2 * np],     aL, &bH[0]);
                mma_bf16(s[2 * np + 1], aH, &bH[2]);
                mma_bf16(s[2 * np + 1], aH, &bL[2]);
                mma_bf16(s[2 * np + 1], aL, &bH[2]);
            }
        }

        // ---- softcap + mask (fragment-local) ----
        const int jb = kb * 64 + ((lane & 3) << 1);
        #pragma unroll
        for (int nt = 0; nt < 8; nt++) {
            #pragma unroll
            for (int u = 0; u < 2; u++) {
                const int ig = q0 + wq * 16 + r0 + u * 8;
                #pragma unroll
                for (int e = 0; e < 2; e++) {
                    const int jg = jb + nt * 8 + e;
                    float x = s[nt][2 * u + e] * 0.0625f;
                    float t = __expf(x * 0.04f);
                    float cc = 50.f * (t - 1.f) / (t + 1.f);
                    bool valid = (jg <= ig) && (ig - jg < WIN);
                    s[nt][2 * u + e] = valid ? cc : -1e30f;
                }
            }
        }
        // ---- online softmax per row (quad shuffles) ----
        #pragma unroll
        for (int u = 0; u < 2; u++) {
            float mx = -1e30f;
            #pragma unroll
            for (int nt = 0; nt < 8; nt++)
                mx = fmaxf(mx, fmaxf(s[nt][2 * u], s[nt][2 * u + 1]));
            mx = fmaxf(mx, __shfl_xor_sync(0xffffffffu, mx, 1));
            mx = fmaxf(mx, __shfl_xor_sync(0xffffffffu, mx, 2));
            float mnew = fmaxf(mrow[u], mx);
            float alpha = __expf(mrow[u] - mnew);
            float rsum = 0.f;
            #pragma unroll
            for (int nt = 0; nt < 8; nt++) {
                #pragma unroll
                for (int e = 0; e < 2; e++) {
                    float sv = s[nt][2 * u + e];
                    float p = (sv < -1e29f) ? 0.f : __expf(sv - mnew);
                    s[nt][2 * u + e] = p;
                    rsum += p;
                }
            }
            rsum += __shfl_xor_sync(0xffffffffu, rsum, 1);
            rsum += __shfl_xor_sync(0xffffffffu, rsum, 2);
            lrow[u] = lrow[u] * alpha + rsum;
            mrow[u] = mnew;
            #pragma unroll
            for (int nt = 0; nt < 16; nt++) {
                o[nt][2 * u]     *= alpha;
                o[nt][2 * u + 1] *= alpha;
            }
        }
        // ---- pack P -> A-fragments (hi + residual) ----
        uint32_t pH[4][4], pL[4][4];
        #pragma unroll
        for (int kc = 0; kc < 4; kc++) {
            pack_split(s[2 * kc][0],     s[2 * kc][1],     pH[kc][0], pL[kc][0]);
            pack_split(s[2 * kc][2],     s[2 * kc][3],     pH[kc][1], pL[kc][1]);
            pack_split(s[2 * kc + 1][0], s[2 * kc + 1][1], pH[kc][2], pL[kc][2]);
            pack_split(s[2 * kc + 1][2], s[2 * kc + 1][3], pH[kc][3], pL[kc][3]);
        }

        asm volatile("cp.async.wait_group 0;" ::: "memory");   // V ready
        __syncthreads();

        // ---- O += P V  (warp's 128-d half) ----
        #pragma unroll
        for (int kc = 0; kc < 4; kc++) {
            #pragma unroll
            for (int nvp = 0; nvp < 8; nvp++) {
                uint32_t vH[4], vL[4];
                uint32_t va = sb + OV_H + (kc * 16 + v_r) * RSB
                            + (wd * 128 + nvp * 16 + v_c) * 2;
                ldsm_x4_t(vH, va);
                ldsm_x4_t(vL, va + ATILE);
                mma_bf16(o[2 * nvp],     pH[kc], &vH[0]);
                mma_bf16(o[2 * nvp],     pH[kc], &vL[0]);
                mma_bf16(o[2 * nvp],     pL[kc], &vH[0]);
                mma_bf16(o[2 * nvp + 1], pH[kc], &vH[2]);
                mma_bf16(o[2 * nvp + 1], pH[kc], &vL[2]);
                mma_bf16(o[2 * nvp + 1], pL[kc], &vH[2]);
            }
        }
        __syncthreads();   // all warps done with K,V before overwrite

        if (kb < qt) {
            const size_t nb = kvbase + (size_t)(kb + 1) * 64 * KCOLS;
            attn_load_half(sb + OK_H, kbh + nb, tid, KCOLS);
            attn_load_half(sb + OK_L, kbl + nb, tid, KCOLS);
            cp_commit();
            attn_load_half(sb + OV_H, vbh + nb, tid, KCOLS);
            attn_load_half(sb + OV_L, vbl + nb, tid, KCOLS);
            cp_commit();
        }
    }

    // ---- epilogue: O/l -> aoH/aoL (bf16 split, feeds final GEMM) ----
    #pragma unroll
    for (int u = 0; u < 2; u++) {
        float rl = 1.f / lrow[u];
        int tok = b * SLEN + q0 + wq * 16 + r0 + u * 8;
        size_t base = (size_t)tok * QCOLS + h * HD + wd * 128 + ((lane & 3) << 1);
        #pragma unroll
        for (int nt = 0; nt < 16; nt++) {
            float x = o[nt][2 * u] * rl;
            float y = o[nt][2 * u + 1] * rl;
            uint32_t hp, lp;
            pack_split(x, y, hp, lp);
            *(uint32_t*)(aoH + base + nt * 8) = hp;
            *(uint32_t*)(aoL + base + nt * 8) = lp;
        }
    }
}

// ---------------------------------------------------------------------------
extern "C" void kernel_launch(void* const* d_in, const int* in_sizes, int n_in,
                              void* d_out, int out_size) {
    const float* hidden = (const float*)d_in[0];
    const int*   pos    = (const int*)d_in[2];
    const float* Wq     = (const float*)d_in[3];
    const float* Wk     = (const float*)d_in[4];
    const float* Wv     = (const float*)d_in[5];
    const float* Wo     = (const float*)d_in[6];
    float* out = (float*)d_out;

    cudaFuncSetAttribute(gemm_mma_kernel,
        cudaFuncAttributeMaxDynamicSharedMemorySize, GSMEM);
    cudaFuncSetAttribute(attn_mma_kernel,
        cudaFuncAttributeMaxDynamicSharedMemorySize, ATTN_SMEM);

    void *hidH, *hidL, *wqH, *wqL, *wkH, *wkL, *wvH, *wvL, *woH, *woL, *aoH, *aoL;
    cudaGetSymbolAddress(&hidH, g_hidH); cudaGetSymbolAddress(&hidL, g_hidL);
    cudaGetSymbolAddress(&wqH, g_wqH);   cudaGetSymbolAddress(&wqL, g_wqL);
    cudaGetSymbolAddress(&wkH, g_wkH);   cudaGetSymbolAddress(&wkL, g_wkL);
    cudaGetSymbolAddress(&wvH, g_wvH);   cudaGetSymbolAddress(&wvL, g_wvL);
    cudaGetSymbolAddress(&woH, g_woH);   cudaGetSymbolAddress(&woL, g_woL);
    cudaGetSymbolAddress(&aoH, g_aoH);   cudaGetSymbolAddress(&aoL, g_aoL);
    void *gq, *gk, *gv;
    cudaGetSymbolAddress(&gq, g_q); cudaGetSymbolAddress(&gk, g_k);
    cudaGetSymbolAddress(&gv, g_v);
    void *qbh, *qbl, *kbh, *kbl, *vbh, *vbl;
    cudaGetSymbolAddress(&qbh, g_qbH); cudaGetSymbolAddress(&qbl, g_qbL);
    cudaGetSymbolAddress(&kbh, g_kbH); cudaGetSymbolAddress(&kbl, g_kbL);
    cudaGetSymbolAddress(&vbh, g_vbH); cudaGetSymbolAddress(&vbl, g_vbL);

    dim3 thr(256);

    // ---- one-time operand conversion ----
    split_kernel<<<(MTOK * HDIM / 4 + 255) / 256, thr>>>(
        hidden, (__nv_bfloat16*)hidH, (__nv_bfloat16*)hidL, MTOK * HDIM);
    transpose_split_kernel<<<dim3(QCOLS / 32, HDIM / 32), thr>>>(
        Wq, (__nv_bfloat16*)wqH, (__nv_bfloat16*)wqL, HDIM, QCOLS);
    transpose_split_kernel<<<dim3(KCOLS / 32, HDIM / 32), thr>>>(
        Wk, (__nv_bfloat16*)wkH, (__nv_bfloat16*)wkL, HDIM, KCOLS);
    transpose_split_kernel<<<dim3(KCOLS / 32, HDIM / 32), thr>>>(
        Wv, (__nv_bfloat16*)wvH, (__nv_bfloat16*)wvL, HDIM, KCOLS);
    transpose_split_kernel<<<dim3(HDIM / 32, QCOLS / 32), thr>>>(
        Wo, (__nv_bfloat16*)woH, (__nv_bfloat16*)woL, QCOLS, HDIM);

    // ---- QKV projections ----
    gemm_mma_kernel<<<dim3(QCOLS / 128, MTOK / 128), thr, GSMEM>>>(
        (__nv_bfloat16*)hidH, (__nv_bfloat16*)hidL,
        (__nv_bfloat16*)wqH, (__nv_bfloat16*)wqL,
        (float*)gq, MTOK, QCOLS, HDIM);
    gemm_mma_kernel<<<dim3(KCOLS / 128, MTOK / 128), thr, GSMEM>>>(
        (__nv_bfloat16*)hidH, (__nv_bfloat16*)hidL,
        (__nv_bfloat16*)wkH, (__nv_bfloat16*)wkL,
        (float*)gk, MTOK, KCOLS, HDIM);
    gemm_mma_kernel<<<dim3(KCOLS / 128, MTOK / 128), thr, GSMEM>>>(
        (__nv_bfloat16*)hidH, (__nv_bfloat16*)hidL,
        (__nv_bfloat16*)wvH, (__nv_bfloat16*)wvL,
        (float*)gv, MTOK, KCOLS, HDIM);

    // ---- RoPE + split Q/K; split V ----
    int rope_threads = MTOK * 12 * 128;
    rope_split_kernel<<<(rope_threads + 255) / 256, thr>>>(pos,
        (__nv_bfloat16*)qbh, (__nv_bfloat16*)qbl,
        (__nv_bfloat16*)kbh, (__nv_bfloat16*)kbl);
    split_kernel<<<(MTOK * KCOLS / 4 + 255) / 256, thr>>>(
        (const float*)gv, (__nv_bfloat16*)vbh, (__nv_bfloat16*)vbl, MTOK * KCOLS);

    // ---- attention (tensor cores) ----
    attn_mma_kernel<<<dim3(SLEN / 64, NHQ, BTCH), thr, ATTN_SMEM>>>(
        (__nv_bfloat16*)qbh, (__nv_bfloat16*)qbl,
        (__nv_bfloat16*)kbh, (__nv_bfloat16*)kbl,
        (__nv_bfloat16*)vbh, (__nv_bfloat16*)vbl,
        (__nv_bfloat16*)aoH, (__nv_bfloat16*)aoL);

    // ---- output projection ----
    gemm_mma_kernel<<<dim3(HDIM / 128, MTOK / 128), thr, GSMEM>>>(
        (__nv_bfloat16*)aoH, (__nv_bfloat16*)aoL,
        (__nv_bfloat16*)woH, (__nv_bfloat16*)woL,
        out, MTOK, HDIM, QCOLS);
}

// round 12
// speedup vs baseline: 1.5406x; 1.5406x over previous
#include <cuda_runtime.h>
#include <cuda_bf16.h>
#include <math.h>
#include <stdint.h>

#define BTCH   2
#define SLEN   2048
#define HDIM   2304
#define NHQ    8
#define NKVH   4
#define HD     256
#define WIN    512
#define MTOK   4096      // B*S
#define QCOLS  2048      // NH*HD
#define KCOLS  1024      // NKV*HD

// ------------------------- scratch (device globals; no allocs allowed) ------
__device__ float g_q[MTOK * QCOLS];
__device__ float g_k[MTOK * KCOLS];
__device__ float g_v[MTOK * KCOLS];

// pre-split bf16 operands (GEMM)
__device__ __align__(16) __nv_bfloat16 g_hidH[MTOK * HDIM], g_hidL[MTOK * HDIM];
__device__ __align__(16) __nv_bfloat16 g_wqH[QCOLS * HDIM], g_wqL[QCOLS * HDIM];
__device__ __align__(16) __nv_bfloat16 g_wkH[KCOLS * HDIM], g_wkL[KCOLS * HDIM];
__device__ __align__(16) __nv_bfloat16 g_wvH[KCOLS * HDIM], g_wvL[KCOLS * HDIM];
__device__ __align__(16) __nv_bfloat16 g_woH[HDIM * QCOLS], g_woL[HDIM * QCOLS];
__device__ __align__(16) __nv_bfloat16 g_aoH[MTOK * QCOLS], g_aoL[MTOK * QCOLS];
// pre-split bf16 Q/K/V (attention)
__device__ __align__(16) __nv_bfloat16 g_qbH[MTOK * QCOLS], g_qbL[MTOK * QCOLS];
__device__ __align__(16) __nv_bfloat16 g_kbH[MTOK * KCOLS], g_kbL[MTOK * KCOLS];
__device__ __align__(16) __nv_bfloat16 g_vbH[MTOK * KCOLS], g_vbL[MTOK * KCOLS];

// ------------------------- helpers -----------------------------------------
__device__ __forceinline__ uint32_t sptr(const void* p) {
    return (uint32_t)__cvta_generic_to_shared(p);
}
__device__ __forceinline__ void ldsm_x4(uint32_t* r, uint32_t a) {
    asm volatile("ldmatrix.sync.aligned.m8n8.x4.shared.b16 {%0,%1,%2,%3}, [%4];"
        : "=r"(r[0]), "=r"(r[1]), "=r"(r[2]), "=r"(r[3]) : "r"(a));
}
__device__ __forceinline__ void ldsm_x4_t(uint32_t* r, uint32_t a) {
    asm volatile("ldmatrix.sync.aligned.m8n8.x4.trans.shared.b16 {%0,%1,%2,%3}, [%4];"
        : "=r"(r[0]), "=r"(r[1]), "=r"(r[2]), "=r"(r[3]) : "r"(a));
}
__device__ __forceinline__ void ldsm_x2(uint32_t* r, uint32_t a) {
    asm volatile("ldmatrix.sync.aligned.m8n8.x2.shared.b16 {%0,%1}, [%2];"
        : "=r"(r[0]), "=r"(r[1]) : "r"(a));
}
__device__ __forceinline__ void mma_bf16(float* c, const uint32_t* a, const uint32_t* b) {
    asm volatile("mma.sync.aligned.m16n8k16.row.col.f32.bf16.bf16.f32 "
        "{%0,%1,%2,%3}, {%4,%5,%6,%7}, {%8,%9}, {%0,%1,%2,%3};"
        : "+f"(c[0]), "+f"(c[1]), "+f"(c[2]), "+f"(c[3])
        : "r"(a[0]), "r"(a[1]), "r"(a[2]), "r"(a[3]), "r"(b[0]), "r"(b[1]));
}
__device__ __forceinline__ void cp_async16(uint32_t dst, const void* src) {
    asm volatile("cp.async.cg.shared.global [%0], [%1], 16;"
        :: "r"(dst), "l"(src) : "memory");
}
__device__ __forceinline__ void cp_commit() {
    asm volatile("cp.async.commit_group;" ::: "memory");
}
__device__ __forceinline__ void split_bf16(float v, __nv_bfloat16& h, __nv_bfloat16& l) {
    h = __float2bfloat16(v);
    l = __float2bfloat16(v - __bfloat162float(h));
}
// pack (x,y) -> bf16x2 hi-part + bf16x2 residual-part
__device__ __forceinline__ void pack_split(float x, float y, uint32_t& hp, uint32_t& lp) {
    uint32_t hh;
    asm("cvt.rn.bf16x2.f32 %0, %1, %2;" : "=r"(hh) : "f"(y), "f"(x));
    float xr = x - __uint_as_float(hh << 16);
    float yr = y - __uint_as_float(hh & 0xffff0000u);
    hp = hh;
    asm("cvt.rn.bf16x2.f32 %0, %1, %2;" : "=r"(lp) : "f"(yr), "f"(xr));
}

// ------------------------- GEMM (unchanged from R6 win) ---------------------
#define KC       32
#define ROWBF    40
#define TILE_B   (128 * ROWBF * 2)
#define STAGE_B  (4 * TILE_B)
#define GSMEM    (2 * STAGE_B)

__device__ __forceinline__ void gemm_load_chunk(
    char* stg, const __nv_bfloat16* Ah, const __nv_bfloat16* Al,
    const __nv_bfloat16* Bh, const __nv_bfloat16* Bl,
    int bm, int bn, int K, int k0, int tid)
{
    const __nv_bfloat16* bases[4] = {Ah, Al, Bh, Bl};
    #pragma unroll
    for (int j = 0; j < 8; j++) {
        const int tile = j >> 1;
        const int e = ((j & 1) << 8) + tid;
        const int row = e >> 2;
        const int c = e & 3;
        const int gr = (tile < 2 ? bm : bn) + row;
        const __nv_bfloat16* src = bases[tile] + (size_t)gr * K + k0 + (c << 3);
        uint32_t dst = sptr(stg + tile * TILE_B + row * (ROWBF * 2) + (c << 4));
        cp_async16(dst, src);
    }
    cp_commit();
}

__global__ void __launch_bounds__(256, 2) gemm_mma_kernel(
    const __nv_bfloat16* __restrict__ Ah, const __nv_bfloat16* __restrict__ Al,
    const __nv_bfloat16* __restrict__ Bh, const __nv_bfloat16* __restrict__ Bl,
    float* __restrict__ C, int M, int N, int K)
{
    extern __shared__ __align__(16) char smem[];
    const int tid  = threadIdx.x;
    const int lane = tid & 31;
    const int warp = tid >> 5;
    const int wm = warp >> 2;
    const int wn = warp & 3;
    const int bm = blockIdx.y * 128;
    const int bn = blockIdx.x * 128;

    float c[4][4][4];
    #pragma unroll
    for (int mt = 0; mt < 4; mt++)
        #pragma unroll
        for (int nt = 0; nt < 4; nt++)
            #pragma unroll
            for (int i = 0; i < 4; i++) c[mt][nt][i] = 0.f;

    const int NC = K / KC;
    gemm_load_chunk(smem, Ah, Al, Bh, Bl, bm, bn, K, 0, tid);

    for (int i = 0; i < NC; i++) {
        if (i + 1 < NC) {
            gemm_load_chunk(smem + ((i + 1) & 1) * STAGE_B,
                            Ah, Al, Bh, Bl, bm, bn, K, (i + 1) * KC, tid);
            asm volatile("cp.async.wait_group 1;" ::: "memory");
        } else {
            asm volatile("cp.async.wait_group 0;" ::: "memory");
        }
        __syncthreads();

        char* stg = smem + (i & 1) * STAGE_B;
        __nv_bfloat16 (*sAh)[ROWBF] = (__nv_bfloat16(*)[ROWBF])(stg);
        __nv_bfloat16 (*sAl)[ROWBF] = (__nv_bfloat16(*)[ROWBF])(stg + TILE_B);
        __nv_bfloat16 (*sBh)[ROWBF] = (__nv_bfloat16(*)[ROWBF])(stg + 2 * TILE_B);
        __nv_bfloat16 (*sBl)[ROWBF] = (__nv_bfloat16(*)[ROWBF])(stg + 3 * TILE_B);

        #pragma unroll
        for (int s = 0; s < 2; s++) {
            uint32_t bh[4][2], bl[4][2];
            const int b_r = lane & 7;
            const int b_c = s * 16 + (((lane >> 3) & 1) << 3);
            #pragma unroll
            for (int nt = 0; nt < 4; nt++) {
                ldsm_x2(bh[nt], sptr(&sBh[wn * 32 + nt * 8 + b_r][b_c]));
                ldsm_x2(bl[nt], sptr(&sBl[wn * 32 + nt * 8 + b_r][b_c]));
            }
            const int a_r = (lane & 7) | (((lane >> 3) & 1) << 3);
            const int a_c = s * 16 + (((lane >> 4) & 1) << 3);
            #pragma unroll
            for (int mt = 0; mt < 4; mt++) {
                uint32_t ah[4], al[4];
                ldsm_x4(ah, sptr(&sAh[wm * 64 + mt * 16 + a_r][a_c]));
                ldsm_x4(al, sptr(&sAl[wm * 64 + mt * 16 + a_r][a_c]));
                #pragma unroll
                for (int nt = 0; nt < 4; nt++) {
                    mma_bf16(c[mt][nt], ah, bh[nt]);
                    mma_bf16(c[mt][nt], ah, bl[nt]);
                    mma_bf16(c[mt][nt], al, bh[nt]);
                }
            }
        }
        __syncthreads();
    }

    #pragma unroll
    for (int mt = 0; mt < 4; mt++) {
        int row = bm + wm * 64 + mt * 16 + (lane >> 2);
        #pragma unroll
        for (int nt = 0; nt < 4; nt++) {
            int col = bn + wn * 32 + nt * 8 + ((lane & 3) << 1);
            *(float2*)(C + (size_t)row * N + col)       = make_float2(c[mt][nt][0], c[mt][nt][1]);
            *(float2*)(C + (size_t)(row + 8) * N + col) = make_float2(c[mt][nt][2], c[mt][nt][3]);
        }
    }
}

// ---------------------------------------------------------------------------
// fp32 -> hi/lo bf16 split
// ---------------------------------------------------------------------------
__global__ void split_kernel(const float* __restrict__ in,
                             __nv_bfloat16* __restrict__ oh,
                             __nv_bfloat16* __restrict__ ol, int n)
{
    int i = (blockIdx.x * blockDim.x + threadIdx.x) << 2;
    if (i >= n) return;
    float4 v = *(const float4*)(in + i);
    float vv[4] = {v.x, v.y, v.z, v.w};
    __nv_bfloat16 h[4], l[4];
    #pragma unroll
    for (int j = 0; j < 4; j++) split_bf16(vv[j], h[j], l[j]);
    *(uint2*)(oh + i) = *(uint2*)h;
    *(uint2*)(ol + i) = *(uint2*)l;
}

// ---------------------------------------------------------------------------
// weight transpose + split: [K][N] fp32 -> [N][K] hi/lo bf16
// ---------------------------------------------------------------------------
__global__ void transpose_split_kernel(const float* __restrict__ W,
                                       __nv_bfloat16* __restrict__ oh,
                                       __nv_bfloat16* __restrict__ ol,
                                       int K, int N)
{
    __shared__ float t[32][33];
    const int k0 = blockIdx.y << 5, n0 = blockIdx.x << 5;
    const int c = threadIdx.x & 31, r = threadIdx.x >> 5;
    #pragma unroll
    for (int it = 0; it < 4; it++) {
        int row = r + (it << 3);
        t[row][c] = W[(size_t)(k0 + row) * N + n0 + c];
    }
    __syncthreads();
    #pragma unroll
    for (int it = 0; it < 4; it++) {
        int n = r + (it << 3);
        float v = t[c][n];
        __nv_bfloat16 h, l;
        split_bf16(v, h, l);
        oh[(size_t)(n0 + n) * K + k0 + c] = h;
        ol[(size_t)(n0 + n) * K + k0 + c] = l;
    }
}

// ---------------------------------------------------------------------------
// RoPE on g_q/g_k fp32, writing split bf16 hi/lo directly.
// ---------------------------------------------------------------------------
__global__ void rope_split_kernel(const int* __restrict__ pos_ids,
    __nv_bfloat16* __restrict__ qbh, __nv_bfloat16* __restrict__ qbl,
    __nv_bfloat16* __restrict__ kbh, __nv_bfloat16* __restrict__ kbl)
{
    int idx = blockIdx.x * blockDim.x + threadIdx.x;
    if (idx >= MTOK * 12 * 128) return;
    int d  = idx & 127;
    int r  = idx >> 7;
    int hh = r % 12;
    int t  = r / 12;
    float pos = (float)pos_ids[t];
    float inv = __expf((float)d * -0.07195578415606394f);
    float ang = pos * inv;
    float sn, cs;
    sincosf(ang, &sn, &cs);
    const float* base;
    size_t ob;
    __nv_bfloat16 *oh, *ol;
    if (hh < 8) {
        base = g_q + (size_t)t * QCOLS + hh * HD;
        ob = (size_t)t * QCOLS + hh * HD + d;
        oh = qbh; ol = qbl;
    } else {
        base = g_k + (size_t)t * KCOLS + (hh - 8) * HD;
        ob = (size_t)t * KCOLS + (hh - 8) * HD + d;
        oh = kbh; ol = kbl;
    }
    float x1 = base[d];
    float x2 = base[d + 128];
    float y1 = x1 * cs - x2 * sn;
    float y2 = x2 * cs + x1 * sn;
    __nv_bfloat16 h1, l1, h2, l2;
    split_bf16(y1, h1, l1);
    split_bf16(y2, h2, l2);
    oh[ob] = h1; ol[ob] = l1;
    oh[ob + 128] = h2; ol[ob + 128] = l2;
}

// ---------------------------------------------------------------------------
// Tensor-core sliding-window flash attention, split-bf16, 2-stage pipeline.
// CTA: 64 queries, 8 warps (wq = q-subtile, wd = d-half for PV).
// KV blocks of 32 keys; stage s loaded while stage s^1 computes.
// ---------------------------------------------------------------------------
#define RSB        528                 // smem row stride bytes (264 bf16)
#define QTILE      (64 * RSB)          // 33792
#define KTILE      (32 * RSB)          // 16896
#define OQ_H       0
#define OQ_L       QTILE
#define OSTG       (2 * QTILE)         // 67584
#define STG_SZ     (4 * KTILE)         // 67584: K_H, K_L, V_H, V_L
#define ATTN_SMEM  (OSTG + 2 * STG_SZ) // 202752

__device__ __forceinline__ void attn_load_q(
    uint32_t dst, const __nv_bfloat16* src, int tid)
{
    #pragma unroll
    for (int j = 0; j < 8; j++) {
        int e = tid + (j << 8);
        int row = e >> 5, c = e & 31;
        cp_async16(dst + row * RSB + (c << 4), src + (size_t)row * QCOLS + (c << 3));
    }
}
// one 32-key stage: K_H, K_L, V_H, V_L; single commit group
__device__ __forceinline__ void attn_load_stage(
    uint32_t sbase, const __nv_bfloat16* kh, const __nv_bfloat16* kl,
    const __nv_bfloat16* vh, const __nv_bfloat16* vl, size_t goff, int tid)
{
    const __nv_bfloat16* srcs[4] = {kh + goff, kl + goff, vh + goff, vl + goff};
    #pragma unroll
    for (int t = 0; t < 4; t++) {
        #pragma unroll
        for (int j = 0; j < 4; j++) {
            int e = tid + (j << 8);
            int row = e >> 5, c = e & 31;
            cp_async16(sbase + t * KTILE + row * RSB + (c << 4),
                       srcs[t] + (size_t)row * KCOLS + (c << 3));
        }
    }
    cp_commit();
}

__global__ void __launch_bounds__(256, 1) attn_mma_kernel(
    const __nv_bfloat16* __restrict__ qbh, const __nv_bfloat16* __restrict__ qbl,
    const __nv_bfloat16* __restrict__ kbh, const __nv_bfloat16* __restrict__ kbl,
    const __nv_bfloat16* __restrict__ vbh, const __nv_bfloat16* __restrict__ vbl,
    __nv_bfloat16* __restrict__ aoH, __nv_bfloat16* __restrict__ aoL)
{
    extern __shared__ __align__(16) char smem[];
    const uint32_t sb = sptr(smem);
    const int qt = blockIdx.x, h = blockIdx.y, b = blockIdx.z;
    const int kvh = h >> 1;
    const int q0 = qt * 64;
    const int tid = threadIdx.x, lane = tid & 31, warp = tid >> 5;
    const int wq = warp & 3, wd = warp >> 2;

    const size_t kvbase = (size_t)(b * SLEN) * KCOLS + kvh * HD;

    // prologue: Q group, then stages 0 and 1
    attn_load_q(sb + OQ_H, qbh + (size_t)(b * SLEN + q0) * QCOLS + h * HD, tid);
    attn_load_q(sb + OQ_L, qbl + (size_t)(b * SLEN + q0) * QCOLS + h * HD, tid);
    cp_commit();

    const int kb_start = (qt * 2 >= 16) ? (qt * 2 - 16) : 0;
    const int kb_end   = qt * 2 + 1;   // inclusive; always >= kb_start+1
    attn_load_stage(sb + OSTG, kbh, kbl, vbh, vbl,
                    kvbase + (size_t)kb_start * 32 * KCOLS, tid);
    attn_load_stage(sb + OSTG + STG_SZ, kbh, kbl, vbh, vbl,
                    kvbase + (size_t)(kb_start + 1) * 32 * KCOLS, tid);

    float o[16][4];
    #pragma unroll
    for (int i = 0; i < 16; i++)
        #pragma unroll
        for (int j = 0; j < 4; j++) o[i][j] = 0.f;
    float mrow[2] = {-1e30f, -1e30f};
    float lrow[2] = {0.f, 0.f};

    const int r0 = lane >> 2;
    const int a_r = (lane & 7) | (((lane >> 3) & 1) << 3);
    const int a_c = ((lane >> 4) & 1) << 3;
    const uint32_t qha = sb + OQ_H + (wq * 16 + a_r) * RSB + a_c * 2;
    const uint32_t qla = sb + OQ_L + (wq * 16 + a_r) * RSB + a_c * 2;
    const int k_r = ((lane >> 4) << 3) + (lane & 7);
    const int k_c = ((lane >> 3) & 1) << 3;
    const int v_r = (((lane >> 3) & 1) << 3) + (lane & 7);
    const int v_c = ((lane >> 4) & 1) << 3;

    for (int kb = kb_start; kb <= kb_end; kb++) {
        const int s = (kb - kb_start) & 1;
        const uint32_t stg = sb + OSTG + s * STG_SZ;
        if (kb < kb_end) {
            asm volatile("cp.async.wait_group 1;" ::: "memory");
        } else {
            asm volatile("cp.async.wait_group 0;" ::: "memory");
        }
        __syncthreads();

        // ---- S = Q K^T (full d=256, 3-product split), 32 keys ----
        float ss[4][4];
        #pragma unroll
        for (int i = 0; i < 4; i++)
            #pragma unroll
            for (int j = 0; j < 4; j++) ss[i][j] = 0.f;

        #pragma unroll 2
        for (int ks = 0; ks < 16; ks++) {
            uint32_t aH[4], aL[4];
            ldsm_x4(aH, qha + ks * 32);
            ldsm_x4(aL, qla + ks * 32);
            #pragma unroll
            for (int np = 0; np < 2; np++) {
                uint32_t bH[4], bL[4];
                uint32_t ka = stg + (np * 16 + k_r) * RSB + (ks * 16 + k_c) * 2;
                ldsm_x4(bH, ka);
                ldsm_x4(bL, ka + KTILE);
                mma_bf16(ss[2 * np],     aH, &bH[0]);
                mma_bf16(ss[2 * np],     aH, &bL[0]);
                mma_bf16(ss[2 * np],     aL, &bH[0]);
                mma_bf16(ss[2 * np + 1], aH, &bH[2]);
                mma_bf16(ss[2 * np + 1], aH, &bL[2]);
                mma_bf16(ss[2 * np + 1], aL, &bH[2]);
            }
        }

        // ---- softcap + mask ----
        const int jb = kb * 32 + ((lane & 3) << 1);
        #pragma unroll
        for (int nt = 0; nt < 4; nt++) {
            #pragma unroll
            for (int u = 0; u < 2; u++) {
                const int ig = q0 + wq * 16 + r0 + u * 8;
                #pragma unroll
                for (int e = 0; e < 2; e++) {
                    const int jg = jb + nt * 8 + e;
                    float x = ss[nt][2 * u + e] * 0.0625f;
                    float t = __expf(x * 0.04f);
                    float cc = 50.f * (t - 1.f) / (t + 1.f);
                    bool valid = (jg <= ig) && (ig - jg < WIN);
                    ss[nt][2 * u + e] = valid ? cc : -1e30f;
                }
            }
        }
        // ---- online softmax (quad shuffles) ----
        #pragma unroll
        for (int u = 0; u < 2; u++) {
            float mx = -1e30f;
            #pragma unroll
            for (int nt = 0; nt < 4; nt++)
                mx = fmaxf(mx, fmaxf(ss[nt][2 * u], ss[nt][2 * u + 1]));
            mx = fmaxf(mx, __shfl_xor_sync(0xffffffffu, mx, 1));
            mx = fmaxf(mx, __shfl_xor_sync(0xffffffffu, mx, 2));
            float mnew = fmaxf(mrow[u], mx);
            float alpha = __expf(mrow[u] - mnew);
            float rsum = 0.f;
            #pragma unroll
            for (int nt = 0; nt < 4; nt++) {
                #pragma unroll
                for (int e = 0; e < 2; e++) {
                    float sv = ss[nt][2 * u + e];
                    float p = (sv < -1e29f) ? 0.f : __expf(sv - mnew);
                    ss[nt][2 * u + e] = p;
                    rsum += p;
                }
            }
            rsum += __shfl_xor_sync(0xffffffffu, rsum, 1);
            rsum += __shfl_xor_sync(0xffffffffu, rsum, 2);
            lrow[u] = lrow[u] * alpha + rsum;
            mrow[u] = mnew;
            #pragma unroll
            for (int nt = 0; nt < 16; nt++) {
                o[nt][2 * u]     *= alpha;
                o[nt][2 * u + 1] *= alpha;
            }
        }
        // ---- pack P -> A-fragments (hi + residual), 2 k16-chunks ----
        uint32_t pH[2][4], pL[2][4];
        #pragma unroll
        for (int kc = 0; kc < 2; kc++) {
            pack_split(ss[2 * kc][0],     ss[2 * kc][1],     pH[kc][0], pL[kc][0]);
            pack_split(ss[2 * kc][2],     ss[2 * kc][3],     pH[kc][1], pL[kc][1]);
            pack_split(ss[2 * kc + 1][0], ss[2 * kc + 1][1], pH[kc][2], pL[kc][2]);
            pack_split(ss[2 * kc + 1][2], ss[2 * kc + 1][3], pH[kc][3], pL[kc][3]);
        }

        // ---- O += P V (warp's 128-d half) ----
        #pragma unroll
        for (int kc = 0; kc < 2; kc++) {
            #pragma unroll
            for (int nvp = 0; nvp < 8; nvp++) {
                uint32_t vH[4], vL[4];
                uint32_t va = stg + 2 * KTILE + (kc * 16 + v_r) * RSB
                            + (wd * 128 + nvp * 16 + v_c) * 2;
                ldsm_x4_t(vH, va);
                ldsm_x4_t(vL, va + KTILE);
                mma_bf16(o[2 * nvp],     pH[kc], &vH[0]);
                mma_bf16(o[2 * nvp],     pH[kc], &vL[0]);
                mma_bf16(o[2 * nvp],     pL[kc], &vH[0]);
                mma_bf16(o[2 * nvp + 1], pH[kc], &vH[2]);
                mma_bf16(o[2 * nvp + 1], pH[kc], &vL[2]);
                mma_bf16(o[2 * nvp + 1], pL[kc], &vH[2]);
            }
        }
        __syncthreads();   // all warps done with stage s before reuse

        if (kb + 2 <= kb_end) {
            attn_load_stage(stg, kbh, kbl, vbh, vbl,
                            kvbase + (size_t)(kb + 2) * 32 * KCOLS, tid);
        }
    }

    // ---- epilogue: O/l -> aoH/aoL (bf16 split, feeds final GEMM) ----
    #pragma unroll
    for (int u = 0; u < 2; u++) {
        float rl = 1.f / lrow[u];
        int tok = b * SLEN + q0 + wq * 16 + r0 + u * 8;
        size_t base = (size_t)tok * QCOLS + h * HD + wd * 128 + ((lane & 3) << 1);
        #pragma unroll
        for (int nt = 0; nt < 16; nt++) {
            float x = o[nt][2 * u] * rl;
            float y = o[nt][2 * u + 1] * rl;
            uint32_t hp, lp;
            pack_split(x, y, hp, lp);
            *(uint32_t*)(aoH + base + nt * 8) = hp;
            *(uint32_t*)(aoL + base + nt * 8) = lp;
        }
    }
}

// ---------------------------------------------------------------------------
extern "C" void kernel_launch(void* const* d_in, const int* in_sizes, int n_in,
                              void* d_out, int out_size) {
    const float* hidden = (const float*)d_in[0];
    const int*   pos    = (const int*)d_in[2];
    const float* Wq     = (const float*)d_in[3];
    const float* Wk     = (const float*)d_in[4];
    const float* Wv     = (const float*)d_in[5];
    const float* Wo     = (const float*)d_in[6];
    float* out = (float*)d_out;

    cudaFuncSetAttribute(gemm_mma_kernel,
        cudaFuncAttributeMaxDynamicSharedMemorySize, GSMEM);
    cudaFuncSetAttribute(attn_mma_kernel,
        cudaFuncAttributeMaxDynamicSharedMemorySize, ATTN_SMEM);

    void *hidH, *hidL, *wqH, *wqL, *wkH, *wkL, *wvH, *wvL, *woH, *woL, *aoH, *aoL;
    cudaGetSymbolAddress(&hidH, g_hidH); cudaGetSymbolAddress(&hidL, g_hidL);
    cudaGetSymbolAddress(&wqH, g_wqH);   cudaGetSymbolAddress(&wqL, g_wqL);
    cudaGetSymbolAddress(&wkH, g_wkH);   cudaGetSymbolAddress(&wkL, g_wkL);
    cudaGetSymbolAddress(&wvH, g_wvH);   cudaGetSymbolAddress(&wvL, g_wvL);
    cudaGetSymbolAddress(&woH, g_woH);   cudaGetSymbolAddress(&woL, g_woL);
    cudaGetSymbolAddress(&aoH, g_aoH);   cudaGetSymbolAddress(&aoL, g_aoL);
    void *gq, *gk, *gv;
    cudaGetSymbolAddress(&gq, g_q); cudaGetSymbolAddress(&gk, g_k);
    cudaGetSymbolAddress(&gv, g_v);
    void *qbh, *qbl, *kbh, *kbl, *vbh, *vbl;
    cudaGetSymbolAddress(&qbh, g_qbH); cudaGetSymbolAddress(&qbl, g_qbL);
    cudaGetSymbolAddress(&kbh, g_kbH); cudaGetSymbolAddress(&kbl, g_kbL);
    cudaGetSymbolAddress(&vbh, g_vbH); cudaGetSymbolAddress(&vbl, g_vbL);

    dim3 thr(256);

    // ---- one-time operand conversion ----
    split_kernel<<<(MTOK * HDIM / 4 + 255) / 256, thr>>>(
        hidden, (__nv_bfloat16*)hidH, (__nv_bfloat16*)hidL, MTOK * HDIM);
    transpose_split_kernel<<<dim3(QCOLS / 32, HDIM / 32), thr>>>(
        Wq, (__nv_bfloat16*)wqH, (__nv_bfloat16*)wqL, HDIM, QCOLS);
    transpose_split_kernel<<<dim3(KCOLS / 32, HDIM / 32), thr>>>(
        Wk, (__nv_bfloat16*)wkH, (__nv_bfloat16*)wkL, HDIM, KCOLS);
    transpose_split_kernel<<<dim3(KCOLS / 32, HDIM / 32), thr>>>(
        Wv, (__nv_bfloat16*)wvH, (__nv_bfloat16*)wvL, HDIM, KCOLS);
    transpose_split_kernel<<<dim3(HDIM / 32, QCOLS / 32), thr>>>(
        Wo, (__nv_bfloat16*)woH, (__nv_bfloat16*)woL, QCOLS, HDIM);

    // ---- QKV projections ----
    gemm_mma_kernel<<<dim3(QCOLS / 128, MTOK / 128), thr, GSMEM>>>(
        (__nv_bfloat16*)hidH, (__nv_bfloat16*)hidL,
        (__nv_bfloat16*)wqH, (__nv_bfloat16*)wqL,
        (float*)gq, MTOK, QCOLS, HDIM);
    gemm_mma_kernel<<<dim3(KCOLS / 128, MTOK / 128), thr, GSMEM>>>(
        (__nv_bfloat16*)hidH, (__nv_bfloat16*)hidL,
        (__nv_bfloat16*)wkH, (__nv_bfloat16*)wkL,
        (float*)gk, MTOK, KCOLS, HDIM);
    gemm_mma_kernel<<<dim3(KCOLS / 128, MTOK / 128), thr, GSMEM>>>(
        (__nv_bfloat16*)hidH, (__nv_bfloat16*)hidL,
        (__nv_bfloat16*)wvH, (__nv_bfloat16*)wvL,
        (float*)gv, MTOK, KCOLS, HDIM);

    // ---- RoPE + split Q/K; split V ----
    int rope_threads = MTOK * 12 * 128;
    rope_split_kernel<<<(rope_threads + 255) / 256, thr>>>(pos,
        (__nv_bfloat16*)qbh, (__nv_bfloat16*)qbl,
        (__nv_bfloat16*)kbh, (__nv_bfloat16*)kbl);
    split_kernel<<<(MTOK * KCOLS / 4 + 255) / 256, thr>>>(
        (const float*)gv, (__nv_bfloat16*)vbh, (__nv_bfloat16*)vbl, MTOK * KCOLS);

    // ---- attention (tensor cores, 2-stage pipeline) ----
    attn_mma_kernel<<<dim3(SLEN / 64, NHQ, BTCH), thr, ATTN_SMEM>>>(
        (__nv_bfloat16*)qbh, (__nv_bfloat16*)qbl,
        (__nv_bfloat16*)kbh, (__nv_bfloat16*)kbl,
        (__nv_bfloat16*)vbh, (__nv_bfloat16*)vbl,
        (__nv_bfloat16*)aoH, (__nv_bfloat16*)aoL);

    // ---- output projection ----
    gemm_mma_kernel<<<dim3(HDIM / 128, MTOK / 128), thr, GSMEM>>>(
        (__nv_bfloat16*)aoH, (__nv_bfloat16*)aoL,
        (__nv_bfloat16*)woH, (__nv_bfloat16*)woL,
        out, MTOK, HDIM, QCOLS);
}

// round 14
// speedup vs baseline: 1.5479x; 1.0048x over previous
#include <cuda_runtime.h>
#include <cuda_bf16.h>
#include <math.h>
#include <stdint.h>

#define BTCH   2
#define SLEN   2048
#define HDIM   2304
#define NHQ    8
#define NKVH   4
#define HD     256
#define WIN    512
#define MTOK   4096      // B*S
#define QCOLS  2048      // NH*HD
#define KCOLS  1024      // NKV*HD

// ------------------------- scratch (device globals; no allocs allowed) ------
__device__ float g_q[MTOK * QCOLS];
__device__ float g_k[MTOK * KCOLS];
__device__ float g_v[MTOK * KCOLS];

// pre-split bf16 operands (GEMM)
__device__ __align__(16) __nv_bfloat16 g_hidH[MTOK * HDIM], g_hidL[MTOK * HDIM];
__device__ __align__(16) __nv_bfloat16 g_wqH[QCOLS * HDIM], g_wqL[QCOLS * HDIM];
__device__ __align__(16) __nv_bfloat16 g_wkH[KCOLS * HDIM], g_wkL[KCOLS * HDIM];
__device__ __align__(16) __nv_bfloat16 g_wvH[KCOLS * HDIM], g_wvL[KCOLS * HDIM];
__device__ __align__(16) __nv_bfloat16 g_woH[HDIM * QCOLS], g_woL[HDIM * QCOLS];
__device__ __align__(16) __nv_bfloat16 g_aoH[MTOK * QCOLS], g_aoL[MTOK * QCOLS];
// pre-split bf16 Q/K/V (attention)
__device__ __align__(16) __nv_bfloat16 g_qbH[MTOK * QCOLS], g_qbL[MTOK * QCOLS];
__device__ __align__(16) __nv_bfloat16 g_kbH[MTOK * KCOLS], g_kbL[MTOK * KCOLS];
__device__ __align__(16) __nv_bfloat16 g_vbH[MTOK * KCOLS], g_vbL[MTOK * KCOLS];

// ------------------------- helpers -----------------------------------------
__device__ __forceinline__ uint32_t sptr(const void* p) {
    return (uint32_t)__cvta_generic_to_shared(p);
}
__device__ __forceinline__ void ldsm_x4(uint32_t* r, uint32_t a) {
    asm volatile("ldmatrix.sync.aligned.m8n8.x4.shared.b16 {%0,%1,%2,%3}, [%4];"
        : "=r"(r[0]), "=r"(r[1]), "=r"(r[2]), "=r"(r[3]) : "r"(a));
}
__device__ __forceinline__ void ldsm_x4_t(uint32_t* r, uint32_t a) {
    asm volatile("ldmatrix.sync.aligned.m8n8.x4.trans.shared.b16 {%0,%1,%2,%3}, [%4];"
        : "=r"(r[0]), "=r"(r[1]), "=r"(r[2]), "=r"(r[3]) : "r"(a));
}
__device__ __forceinline__ void ldsm_x2(uint32_t* r, uint32_t a) {
    asm volatile("ldmatrix.sync.aligned.m8n8.x2.shared.b16 {%0,%1}, [%2];"
        : "=r"(r[0]), "=r"(r[1]) : "r"(a));
}
__device__ __forceinline__ void mma_bf16(float* c, const uint32_t* a, const uint32_t* b) {
    asm volatile("mma.sync.aligned.m16n8k16.row.col.f32.bf16.bf16.f32 "
        "{%0,%1,%2,%3}, {%4,%5,%6,%7}, {%8,%9}, {%0,%1,%2,%3};"
        : "+f"(c[0]), "+f"(c[1]), "+f"(c[2]), "+f"(c[3])
        : "r"(a[0]), "r"(a[1]), "r"(a[2]), "r"(a[3]), "r"(b[0]), "r"(b[1]));
}
__device__ __forceinline__ void cp_async16(uint32_t dst, const void* src) {
    asm volatile("cp.async.cg.shared.global [%0], [%1], 16;"
        :: "r"(dst), "l"(src) : "memory");
}
__device__ __forceinline__ void cp_commit() {
    asm volatile("cp.async.commit_group;" ::: "memory");
}
__device__ __forceinline__ void split_bf16(float v, __nv_bfloat16& h, __nv_bfloat16& l) {
    h = __float2bfloat16(v);
    l = __float2bfloat16(v - __bfloat162float(h));
}
// pack (x,y) -> bf16x2 hi-part + bf16x2 residual-part
__device__ __forceinline__ void pack_split(float x, float y, uint32_t& hp, uint32_t& lp) {
    uint32_t hh;
    asm("cvt.rn.bf16x2.f32 %0, %1, %2;" : "=r"(hh) : "f"(y), "f"(x));
    float xr = x - __uint_as_float(hh << 16);
    float yr = y - __uint_as_float(hh & 0xffff0000u);
    hp = hh;
    asm("cvt.rn.bf16x2.f32 %0, %1, %2;" : "=r"(lp) : "f"(yr), "f"(xr));
}

// ------------------------- GEMM --------------------------------------------
#define KC       32
#define ROWBF    40
#define TILE_B   (128 * ROWBF * 2)
#define STAGE_B  (4 * TILE_B)
#define GSMEM    (2 * STAGE_B)

__device__ __forceinline__ void gemm_load_chunk(
    char* stg, const __nv_bfloat16* Ah, const __nv_bfloat16* Al,
    const __nv_bfloat16* Bh, const __nv_bfloat16* Bl,
    int bm, int bn, int K, int k0, int tid)
{
    const __nv_bfloat16* bases[4] = {Ah, Al, Bh, Bl};
    #pragma unroll
    for (int j = 0; j < 8; j++) {
        const int tile = j >> 1;
        const int e = ((j & 1) << 8) + tid;
        const int row = e >> 2;
        const int c = e & 3;
        const int gr = (tile < 2 ? bm : bn) + row;
        const __nv_bfloat16* src = bases[tile] + (size_t)gr * K + k0 + (c << 3);
        uint32_t dst = sptr(stg + tile * TILE_B + row * (ROWBF * 2) + (c << 4));
        cp_async16(dst, src);
    }
    cp_commit();
}

__global__ void __launch_bounds__(256, 2) gemm_mma_kernel(
    const __nv_bfloat16* __restrict__ Ah, const __nv_bfloat16* __restrict__ Al,
    const __nv_bfloat16* __restrict__ Bh, const __nv_bfloat16* __restrict__ Bl,
    float* __restrict__ C, int M, int N, int K)
{
    extern __shared__ __align__(16) char smem[];
    const int tid  = threadIdx.x;
    const int lane = tid & 31;
    const int warp = tid >> 5;
    const int wm = warp >> 2;
    const int wn = warp & 3;
    const int bm = blockIdx.y * 128;
    const int bn = blockIdx.x * 128;

    float c[4][4][4];
    #pragma unroll
    for (int mt = 0; mt < 4; mt++)
        #pragma unroll
        for (int nt = 0; nt < 4; nt++)
            #pragma unroll
            for (int i = 0; i < 4; i++) c[mt][nt][i] = 0.f;

    const int NC = K / KC;
    gemm_load_chunk(smem, Ah, Al, Bh, Bl, bm, bn, K, 0, tid);

    for (int i = 0; i < NC; i++) {
        if (i + 1 < NC) {
            gemm_load_chunk(smem + ((i + 1) & 1) * STAGE_B,
                            Ah, Al, Bh, Bl, bm, bn, K, (i + 1) * KC, tid);
            asm volatile("cp.async.wait_group 1;" ::: "memory");
        } else {
            asm volatile("cp.async.wait_group 0;" ::: "memory");
        }
        __syncthreads();

        char* stg = smem + (i & 1) * STAGE_B;
        __nv_bfloat16 (*sAh)[ROWBF] = (__nv_bfloat16(*)[ROWBF])(stg);
        __nv_bfloat16 (*sAl)[ROWBF] = (__nv_bfloat16(*)[ROWBF])(stg + TILE_B);
        __nv_bfloat16 (*sBh)[ROWBF] = (__nv_bfloat16(*)[ROWBF])(stg + 2 * TILE_B);
        __nv_bfloat16 (*sBl)[ROWBF] = (__nv_bfloat16(*)[ROWBF])(stg + 3 * TILE_B);

        #pragma unroll
        for (int s = 0; s < 2; s++) {
            uint32_t bh[4][2], bl[4][2];
            const int b_r = lane & 7;
            const int b_c = s * 16 + (((lane >> 3) & 1) << 3);
            #pragma unroll
            for (int nt = 0; nt < 4; nt++) {
                ldsm_x2(bh[nt], sptr(&sBh[wn * 32 + nt * 8 + b_r][b_c]));
                ldsm_x2(bl[nt], sptr(&sBl[wn * 32 + nt * 8 + b_r][b_c]));
            }
            const int a_r = (lane & 7) | (((lane >> 3) & 1) << 3);
            const int a_c = s * 16 + (((lane >> 4) & 1) << 3);
            #pragma unroll
            for (int mt = 0; mt < 4; mt++) {
                uint32_t ah[4], al[4];
                ldsm_x4(ah, sptr(&sAh[wm * 64 + mt * 16 + a_r][a_c]));
                ldsm_x4(al, sptr(&sAl[wm * 64 + mt * 16 + a_r][a_c]));
                // product-major: same accumulator revisited at distance 4
                #pragma unroll
                for (int nt = 0; nt < 4; nt++) mma_bf16(c[mt][nt], ah, bh[nt]);
                #pragma unroll
                for (int nt = 0; nt < 4; nt++) mma_bf16(c[mt][nt], ah, bl[nt]);
                #pragma unroll
                for (int nt = 0; nt < 4; nt++) mma_bf16(c[mt][nt], al, bh[nt]);
            }
        }
        __syncthreads();
    }

    #pragma unroll
    for (int mt = 0; mt < 4; mt++) {
        int row = bm + wm * 64 + mt * 16 + (lane >> 2);
        #pragma unroll
        for (int nt = 0; nt < 4; nt++) {
            int col = bn + wn * 32 + nt * 8 + ((lane & 3) << 1);
            *(float2*)(C + (size_t)row * N + col)       = make_float2(c[mt][nt][0], c[mt][nt][1]);
            *(float2*)(C + (size_t)(row + 8) * N + col) = make_float2(c[mt][nt][2], c[mt][nt][3]);
        }
    }
}

// ---------------------------------------------------------------------------
// fp32 -> hi/lo bf16 split
// ---------------------------------------------------------------------------
__global__ void split_kernel(const float* __restrict__ in,
                             __nv_bfloat16* __restrict__ oh,
                             __nv_bfloat16* __restrict__ ol, int n)
{
    int i = (blockIdx.x * blockDim.x + threadIdx.x) << 2;
    if (i >= n) return;
    float4 v = *(const float4*)(in + i);
    float vv[4] = {v.x, v.y, v.z, v.w};
    __nv_bfloat16 h[4], l[4];
    #pragma unroll
    for (int j = 0; j < 4; j++) split_bf16(vv[j], h[j], l[j]);
    *(uint2*)(oh + i) = *(uint2*)h;
    *(uint2*)(ol + i) = *(uint2*)l;
}

// ---------------------------------------------------------------------------
// weight transpose + split: [K][N] fp32 -> [N][K] hi/lo bf16
// ---------------------------------------------------------------------------
__global__ void transpose_split_kernel(const float* __restrict__ W,
                                       __nv_bfloat16* __restrict__ oh,
                                       __nv_bfloat16* __restrict__ ol,
                                       int K, int N)
{
    __shared__ float t[32][33];
    const int k0 = blockIdx.y << 5, n0 = blockIdx.x << 5;
    const int c = threadIdx.x & 31, r = threadIdx.x >> 5;
    #pragma unroll
    for (int it = 0; it < 4; it++) {
        int row = r + (it << 3);
        t[row][c] = W[(size_t)(k0 + row) * N + n0 + c];
    }
    __syncthreads();
    #pragma unroll
    for (int it = 0; it < 4; it++) {
        int n = r + (it << 3);
        float v = t[c][n];
        __nv_bfloat16 h, l;
        split_bf16(v, h, l);
        oh[(size_t)(n0 + n) * K + k0 + c] = h;
        ol[(size_t)(n0 + n) * K + k0 + c] = l;
    }
}

// ---------------------------------------------------------------------------
// RoPE on g_q/g_k fp32, writing split bf16 hi/lo directly.
// ---------------------------------------------------------------------------
__global__ void rope_split_kernel(const int* __restrict__ pos_ids,
    __nv_bfloat16* __restrict__ qbh, __nv_bfloat16* __restrict__ qbl,
    __nv_bfloat16* __restrict__ kbh, __nv_bfloat16* __restrict__ kbl)
{
    int idx = blockIdx.x * blockDim.x + threadIdx.x;
    if (idx >= MTOK * 12 * 128) return;
    int d  = idx & 127;
    int r  = idx >> 7;
    int hh = r % 12;
    int t  = r / 12;
    float pos = (float)pos_ids[t];
    float inv = __expf((float)d * -0.07195578415606394f);
    float ang = pos * inv;
    float sn, cs;
    sincosf(ang, &sn, &cs);
    const float* base;
    size_t ob;
    __nv_bfloat16 *oh, *ol;
    if (hh < 8) {
        base = g_q + (size_t)t * QCOLS + hh * HD;
        ob = (size_t)t * QCOLS + hh * HD + d;
        oh = qbh; ol = qbl;
    } else {
        base = g_k + (size_t)t * KCOLS + (hh - 8) * HD;
        ob = (size_t)t * KCOLS + (hh - 8) * HD + d;
        oh = kbh; ol = kbl;
    }
    float x1 = base[d];
    float x2 = base[d + 128];
    float y1 = x1 * cs - x2 * sn;
    float y2 = x2 * cs + x1 * sn;
    __nv_bfloat16 h1, l1, h2, l2;
    split_bf16(y1, h1, l1);
    split_bf16(y2, h2, l2);
    oh[ob] = h1; ol[ob] = l1;
    oh[ob + 128] = h2; ol[ob + 128] = l2;
}

// ---------------------------------------------------------------------------
// Tensor-core sliding-window flash attention, split-bf16, 2-stage pipeline.
// Q-hi fragments register-cached; all mma loops product-major (RAW spacing).
// ---------------------------------------------------------------------------
#define RSB        528                 // smem row stride bytes (264 bf16)
#define QTILE      (64 * RSB)          // 33792
#define KTILE      (32 * RSB)          // 16896
#define OQ_H       0
#define OQ_L       QTILE
#define OSTG       (2 * QTILE)         // 67584
#define STG_SZ     (4 * KTILE)         // 67584: K_H, K_L, V_H, V_L
#define ATTN_SMEM  (OSTG + 2 * STG_SZ) // 202752

__device__ __forceinline__ void attn_load_q(
    uint32_t dst, const __nv_bfloat16* src, int tid)
{
    #pragma unroll
    for (int j = 0; j < 8; j++) {
        int e = tid + (j << 8);
        int row = e >> 5, c = e & 31;
        cp_async16(dst + row * RSB + (c << 4), src + (size_t)row * QCOLS + (c << 3));
    }
}
// one 32-key stage: K_H, K_L, V_H, V_L; single commit group
__device__ __forceinline__ void attn_load_stage(
    uint32_t sbase, const __nv_bfloat16* kh, const __nv_bfloat16* kl,
    const __nv_bfloat16* vh, const __nv_bfloat16* vl, size_t goff, int tid)
{
    const __nv_bfloat16* srcs[4] = {kh + goff, kl + goff, vh + goff, vl + goff};
    #pragma unroll
    for (int t = 0; t < 4; t++) {
        #pragma unroll
        for (int j = 0; j < 4; j++) {
            int e = tid + (j << 8);
            int row = e >> 5, c = e & 31;
            cp_async16(sbase + t * KTILE + row * RSB + (c << 4),
                       srcs[t] + (size_t)row * KCOLS + (c << 3));
        }
    }
    cp_commit();
}

__global__ void __launch_bounds__(256, 1) attn_mma_kernel(
    const __nv_bfloat16* __restrict__ qbh, const __nv_bfloat16* __restrict__ qbl,
    const __nv_bfloat16* __restrict__ kbh, const __nv_bfloat16* __restrict__ kbl,
    const __nv_bfloat16* __restrict__ vbh, const __nv_bfloat16* __restrict__ vbl,
    __nv_bfloat16* __restrict__ aoH, __nv_bfloat16* __restrict__ aoL)
{
    extern __shared__ __align__(16) char smem[];
    const uint32_t sb = sptr(smem);
    const int qt = blockIdx.x, h = blockIdx.y, b = blockIdx.z;
    const int kvh = h >> 1;
    const int q0 = qt * 64;
    const int tid = threadIdx.x, lane = tid & 31, warp = tid >> 5;
    const int wq = warp & 3, wd = warp >> 2;

    const size_t kvbase = (size_t)(b * SLEN) * KCOLS + kvh * HD;

    // prologue: Q group, then stages 0 and 1
    attn_load_q(sb + OQ_H, qbh + (size_t)(b * SLEN + q0) * QCOLS + h * HD, tid);
    attn_load_q(sb + OQ_L, qbl + (size_t)(b * SLEN + q0) * QCOLS + h * HD, tid);
    cp_commit();

    const int kb_start = (qt * 2 >= 16) ? (qt * 2 - 16) : 0;
    const int kb_end   = qt * 2 + 1;   // inclusive
    attn_load_stage(sb + OSTG, kbh, kbl, vbh, vbl,
                    kvbase + (size_t)kb_start * 32 * KCOLS, tid);
    attn_load_stage(sb + OSTG + STG_SZ, kbh, kbl, vbh, vbl,
                    kvbase + (size_t)(kb_start + 1) * 32 * KCOLS, tid);

    float o[16][4];
    #pragma unroll
    for (int i = 0; i < 16; i++)
        #pragma unroll
        for (int j = 0; j < 4; j++) o[i][j] = 0.f;
    float mrow[2] = {-1e30f, -1e30f};
    float lrow[2] = {0.f, 0.f};

    const int r0 = lane >> 2;
    const int a_r = (lane & 7) | (((lane >> 3) & 1) << 3);
    const int a_c = ((lane >> 4) & 1) << 3;
    const uint32_t qha = sb + OQ_H + (wq * 16 + a_r) * RSB + a_c * 2;
    const uint32_t qla = sb + OQ_L + (wq * 16 + a_r) * RSB + a_c * 2;
    const int k_r = ((lane >> 4) << 3) + (lane & 7);
    const int k_c = ((lane >> 3) & 1) << 3;
    const int v_r = (((lane >> 3) & 1) << 3) + (lane & 7);
    const int v_c = ((lane >> 4) & 1) << 3;

    // ---- cache invariant Q-hi fragments in registers (Q group done) ----
    asm volatile("cp.async.wait_group 2;" ::: "memory");
    __syncthreads();
    uint32_t qfH[16][4];
    #pragma unroll
    for (int ks = 0; ks < 16; ks++) ldsm_x4(qfH[ks], qha + ks * 32);

    for (int kb = kb_start; kb <= kb_end; kb++) {
        const int s = (kb - kb_start) & 1;
        const uint32_t stg = sb + OSTG + s * STG_SZ;
        if (kb < kb_end) {
            asm volatile("cp.async.wait_group 1;" ::: "memory");
        } else {
            asm volatile("cp.async.wait_group 0;" ::: "memory");
        }
        __syncthreads();

        // ---- S = Q K^T (full d=256, 3-product split), 32 keys ----
        float ss[4][4];
        #pragma unroll
        for (int i = 0; i < 4; i++)
            #pragma unroll
            for (int j = 0; j < 4; j++) ss[i][j] = 0.f;

        #pragma unroll
        for (int ks = 0; ks < 16; ks++) {
            uint32_t aL[4];
            ldsm_x4(aL, qla + ks * 32);
            uint32_t bH[2][4], bL[2][4];
            #pragma unroll
            for (int np = 0; np < 2; np++) {
                uint32_t ka = stg + (np * 16 + k_r) * RSB + (ks * 16 + k_c) * 2;
                ldsm_x4(bH[np], ka);
                ldsm_x4(bL[np], ka + KTILE);
            }
            // product-major: each accumulator revisited at distance 4
            #pragma unroll
            for (int np = 0; np < 2; np++) {
                mma_bf16(ss[2 * np],     qfH[ks], &bH[np][0]);
                mma_bf16(ss[2 * np + 1], qfH[ks], &bH[np][2]);
            }
            #pragma unroll
            for (int np = 0; np < 2; np++) {
                mma_bf16(ss[2 * np],     qfH[ks], &bL[np][0]);
                mma_bf16(ss[2 * np + 1], qfH[ks], &bL[np][2]);
            }
            #pragma unroll
            for (int np = 0; np < 2; np++) {
                mma_bf16(ss[2 * np],     aL, &bH[np][0]);
                mma_bf16(ss[2 * np + 1], aL, &bH[np][2]);
            }
        }

        // ---- softcap + mask ----
        const int jb = kb * 32 + ((lane & 3) << 1);
        #pragma unroll
        for (int nt = 0; nt < 4; nt++) {
            #pragma unroll
            for (int u = 0; u < 2; u++) {
                const int ig = q0 + wq * 16 + r0 + u * 8;
                #pragma unroll
                for (int e = 0; e < 2; e++) {
                    const int jg = jb + nt * 8 + e;
                    float x = ss[nt][2 * u + e] * 0.0625f;
                    float t = __expf(x * 0.04f);
                    float cc = 50.f * (t - 1.f) / (t + 1.f);
                    bool valid = (jg <= ig) && (ig - jg < WIN);
                    ss[nt][2 * u + e] = valid ? cc : -1e30f;
                }
            }
        }
        // ---- online softmax (quad shuffles) ----
        #pragma unroll
        for (int u = 0; u < 2; u++) {
            float mx = -1e30f;
            #pragma unroll
            for (int nt = 0; nt < 4; nt++)
                mx = fmaxf(mx, fmaxf(ss[nt][2 * u], ss[nt][2 * u + 1]));
            mx = fmaxf(mx, __shfl_xor_sync(0xffffffffu, mx, 1));
            mx = fmaxf(mx, __shfl_xor_sync(0xffffffffu, mx, 2));
            float mnew = fmaxf(mrow[u], mx);
            float alpha = __expf(mrow[u] - mnew);
            float rsum = 0.f;
            #pragma unroll
            for (int nt = 0; nt < 4; nt++) {
                #pragma unroll
                for (int e = 0; e < 2; e++) {
                    float sv = ss[nt][2 * u + e];
                    float p = (sv < -1e29f) ? 0.f : __expf(sv - mnew);
                    ss[nt][2 * u + e] = p;
                    rsum += p;
                }
            }
            rsum += __shfl_xor_sync(0xffffffffu, rsum, 1);
            rsum += __shfl_xor_sync(0xffffffffu, rsum, 2);
            lrow[u] = lrow[u] * alpha + rsum;
            mrow[u] = mnew;
            #pragma unroll
            for (int nt = 0; nt < 16; nt++) {
                o[nt][2 * u]     *= alpha;
                o[nt][2 * u + 1] *= alpha;
            }
        }
        // ---- pack P -> A-fragments (hi + residual), 2 k16-chunks ----
        uint32_t pH[2][4], pL[2][4];
        #pragma unroll
        for (int kc = 0; kc < 2; kc++) {
            pack_split(ss[2 * kc][0],     ss[2 * kc][1],     pH[kc][0], pL[kc][0]);
            pack_split(ss[2 * kc][2],     ss[2 * kc][3],     pH[kc][1], pL[kc][1]);
            pack_split(ss[2 * kc + 1][0], ss[2 * kc + 1][1], pH[kc][2], pL[kc][2]);
            pack_split(ss[2 * kc + 1][2], ss[2 * kc + 1][3], pH[kc][3], pL[kc][3]);
        }

        // ---- O += P V (warp's 128-d half), nvp-paired product-major ----
        #pragma unroll
        for (int kc = 0; kc < 2; kc++) {
            #pragma unroll
            for (int g = 0; g < 4; g++) {
                uint32_t vH[2][4], vL[2][4];
                #pragma unroll
                for (int j = 0; j < 2; j++) {
                    int nvp = g * 2 + j;
                    uint32_t va = stg + 2 * KTILE + (kc * 16 + v_r) * RSB
                                + (wd * 128 + nvp * 16 + v_c) * 2;
                    ldsm_x4_t(vH[j], va);
                    ldsm_x4_t(vL[j], va + KTILE);
                }
                #pragma unroll
                for (int j = 0; j < 2; j++) {
                    int nvp = g * 2 + j;
                    mma_bf16(o[2 * nvp],     pH[kc], &vH[j][0]);
                    mma_bf16(o[2 * nvp + 1], pH[kc], &vH[j][2]);
                }
                #pragma unroll
                for (int j = 0; j < 2; j++) {
                    int nvp = g * 2 + j;
                    mma_bf16(o[2 * nvp],     pH[kc], &vL[j][0]);
                    mma_bf16(o[2 * nvp + 1], pH[kc], &vL[j][2]);
                }
                #pragma unroll
                for (int j = 0; j < 2; j++) {
                    int nvp = g * 2 + j;
                    mma_bf16(o[2 * nvp],     pL[kc], &vH[j][0]);
                    mma_bf16(o[2 * nvp + 1], pL[kc], &vH[j][2]);
                }
            }
        }
        __syncthreads();   // all warps done with stage s before reuse

        if (kb + 2 <= kb_end) {
            attn_load_stage(stg, kbh, kbl, vbh, vbl,
                            kvbase + (size_t)(kb + 2) * 32 * KCOLS, tid);
        }
    }

    // ---- epilogue: O/l -> aoH/aoL (bf16 split, feeds final GEMM) ----
    #pragma unroll
    for (int u = 0; u < 2; u++) {
        float rl = 1.f / lrow[u];
        int tok = b * SLEN + q0 + wq * 16 + r0 + u * 8;
        size_t base = (size_t)tok * QCOLS + h * HD + wd * 128 + ((lane & 3) << 1);
        #pragma unroll
        for (int nt = 0; nt < 16; nt++) {
            float x = o[nt][2 * u] * rl;
            float y = o[nt][2 * u + 1] * rl;
            uint32_t hp, lp;
            pack_split(x, y, hp, lp);
            *(uint32_t*)(aoH + base + nt * 8) = hp;
            *(uint32_t*)(aoL + base + nt * 8) = lp;
        }
    }
}

// ---------------------------------------------------------------------------
extern "C" void kernel_launch(void* const* d_in, const int* in_sizes, int n_in,
                              void* d_out, int out_size) {
    const float* hidden = (const float*)d_in[0];
    const int*   pos    = (const int*)d_in[2];
    const float* Wq     = (const float*)d_in[3];
    const float* Wk     = (const float*)d_in[4];
    const float* Wv     = (const float*)d_in[5];
    const float* Wo     = (const float*)d_in[6];
    float* out = (float*)d_out;

    cudaFuncSetAttribute(gemm_mma_kernel,
        cudaFuncAttributeMaxDynamicSharedMemorySize, GSMEM);
    cudaFuncSetAttribute(attn_mma_kernel,
        cudaFuncAttributeMaxDynamicSharedMemorySize, ATTN_SMEM);

    void *hidH, *hidL, *wqH, *wqL, *wkH, *wkL, *wvH, *wvL, *woH, *woL, *aoH, *aoL;
    cudaGetSymbolAddress(&hidH, g_hidH); cudaGetSymbolAddress(&hidL, g_hidL);
    cudaGetSymbolAddress(&wqH, g_wqH);   cudaGetSymbolAddress(&wqL, g_wqL);
    cudaGetSymbolAddress(&wkH, g_wkH);   cudaGetSymbolAddress(&wkL, g_wkL);
    cudaGetSymbolAddress(&wvH, g_wvH);   cudaGetSymbolAddress(&wvL, g_wvL);
    cudaGetSymbolAddress(&woH, g_woH);   cudaGetSymbolAddress(&woL, g_woL);
    cudaGetSymbolAddress(&aoH, g_aoH);   cudaGetSymbolAddress(&aoL, g_aoL);
    void *gq, *gk, *gv;
    cudaGetSymbolAddress(&gq, g_q); cudaGetSymbolAddress(&gk, g_k);
    cudaGetSymbolAddress(&gv, g_v);
    void *qbh, *qbl, *kbh, *kbl, *vbh, *vbl;
    cudaGetSymbolAddress(&qbh, g_qbH); cudaGetSymbolAddress(&qbl, g_qbL);
    cudaGetSymbolAddress(&kbh, g_kbH); cudaGetSymbolAddress(&kbl, g_kbL);
    cudaGetSymbolAddress(&vbh, g_vbH); cudaGetSymbolAddress(&vbl, g_vbL);

    dim3 thr(256);

    // ---- one-time operand conversion ----
    split_kernel<<<(MTOK * HDIM / 4 + 255) / 256, thr>>>(
        hidden, (__nv_bfloat16*)hidH, (__nv_bfloat16*)hidL, MTOK * HDIM);
    transpose_split_kernel<<<dim3(QCOLS / 32, HDIM / 32), thr>>>(
        Wq, (__nv_bfloat16*)wqH, (__nv_bfloat16*)wqL, HDIM, QCOLS);
    transpose_split_kernel<<<dim3(KCOLS / 32, HDIM / 32), thr>>>(
        Wk, (__nv_bfloat16*)wkH, (__nv_bfloat16*)wkL, HDIM, KCOLS);
    transpose_split_kernel<<<dim3(KCOLS / 32, HDIM / 32), thr>>>(
        Wv, (__nv_bfloat16*)wvH, (__nv_bfloat16*)wvL, HDIM, KCOLS);
    transpose_split_kernel<<<dim3(HDIM / 32, QCOLS / 32), thr>>>(
        Wo, (__nv_bfloat16*)woH, (__nv_bfloat16*)woL, QCOLS, HDIM);

    // ---- QKV projections ----
    gemm_mma_kernel<<<dim3(QCOLS / 128, MTOK / 128), thr, GSMEM>>>(
        (__nv_bfloat16*)hidH, (__nv_bfloat16*)hidL,
        (__nv_bfloat16*)wqH, (__nv_bfloat16*)wqL,
        (float*)gq, MTOK, QCOLS, HDIM);
    gemm_mma_kernel<<<dim3(KCOLS / 128, MTOK / 128), thr, GSMEM>>>(
        (__nv_bfloat16*)hidH, (__nv_bfloat16*)hidL,
        (__nv_bfloat16*)wkH, (__nv_bfloat16*)wkL,
        (float*)gk, MTOK, KCOLS, HDIM);
    gemm_mma_kernel<<<dim3(KCOLS / 128, MTOK / 128), thr, GSMEM>>>(
        (__nv_bfloat16*)hidH, (__nv_bfloat16*)hidL,
        (__nv_bfloat16*)wvH, (__nv_bfloat16*)wvL,
        (float*)gv, MTOK, KCOLS, HDIM);

    // ---- RoPE + split Q/K; split V ----
    int rope_threads = MTOK * 12 * 128;
    rope_split_kernel<<<(rope_threads + 255) / 256, thr>>>(pos,
        (__nv_bfloat16*)qbh, (__nv_bfloat16*)qbl,
        (__nv_bfloat16*)kbh, (__nv_bfloat16*)kbl);
    split_kernel<<<(MTOK * KCOLS / 4 + 255) / 256, thr>>>(
        (const float*)gv, (__nv_bfloat16*)vbh, (__nv_bfloat16*)vbl, MTOK * KCOLS);

    // ---- attention (tensor cores, 2-stage pipeline) ----
    attn_mma_kernel<<<dim3(SLEN / 64, NHQ, BTCH), thr, ATTN_SMEM>>>(
        (__nv_bfloat16*)qbh, (__nv_bfloat16*)qbl,
        (__nv_bfloat16*)kbh, (__nv_bfloat16*)kbl,
        (__nv_bfloat16*)vbh, (__nv_bfloat16*)vbl,
        (__nv_bfloat16*)aoH, (__nv_bfloat16*)aoL);

    // ---- output projection ----
    gemm_mma_kernel<<<dim3(HDIM / 128, MTOK / 128), thr, GSMEM>>>(
        (__nv_bfloat16*)aoH, (__nv_bfloat16*)aoL,
        (__nv_bfloat16*)woH, (__nv_bfloat16*)woL,
        out, MTOK, HDIM, QCOLS);
}